// round 16
// baseline (speedup 1.0000x reference)
#include <cuda_runtime.h>
#include <cuda_fp16.h>
#include <cstdint>

// ---------------- problem constants ----------------
#define ND 50000
#define NP 20000
#define ED 65536
#define EP 65536
#define BB 4096
#define EPS 1e-5f
#define CAP_D 32
#define CAP_P 64

// padded K dims (multiples of 32)
#define KP_GD 1024
#define KP_GP 2816
#define KP_F0 3392
#define KP_Z1 2048
#define KP_F  1024

// ---------------- scratch (zero-initialized at module load; re-zeroed at end of each run) ----------------
__device__ float g_degd[ND];
__device__ float g_degp[NP];
__device__ int   g_cntd[ND];
__device__ int   g_cntp[NP];
__device__ int   g_ebufd[(size_t)ND * CAP_D];
__device__ int   g_ebufp[(size_t)NP * CAP_P];
__device__ float g_z1[(size_t)BB * 2048];
__device__ float g_z2[(size_t)BB * 1024];
__device__ float g_z3[(size_t)BB * 256];
#define STATS_TOTAL 6656
__device__ float g_stats[STATS_TOTAL];

// A-side fp16 hi/lo, fragment-major A' layout (tile 256m x 32k)
__device__ __half g_Gdh[(size_t)BB * KP_GD], g_Gdl[(size_t)BB * KP_GD];
__device__ __half g_Gph[(size_t)BB * KP_GP], g_Gpl[(size_t)BB * KP_GP];
__device__ __half g_F0h[(size_t)BB * KP_F0], g_F0l[(size_t)BB * KP_F0];
__device__ __half g_Z1h[(size_t)BB * KP_Z1], g_Z1l[(size_t)BB * KP_Z1];
__device__ __half g_Fh[(size_t)BB * KP_F],   g_Fl[(size_t)BB * KP_F];
// B-side fp16 hi only, fragment-major B' layout (tile 128n x 32k)
__device__ __half g_Wdgh[(size_t)KP_GD * 1024];
__device__ __half g_Wpgh[(size_t)KP_GP * 1024];
__device__ __half g_We1h[(size_t)KP_F0 * 2048];
__device__ __half g_We2h[(size_t)KP_Z1 * 1024];
__device__ __half g_Wo1h[(size_t)KP_F * 256];

__device__ __forceinline__ float lrelu(float x) { return x >= 0.f ? x : 0.01f * x; }

__device__ __forceinline__ void split_h(float f, __half& hi, __half& lo) {
    hi = __float2half_rn(f);
    lo = __float2half_rn(f - __half2float(hi));
}

__device__ __forceinline__ uint32_t pack2(__half a, __half b) {
    __half2 h = __halves2half2(a, b);
    return *reinterpret_cast<uint32_t*>(&h);
}

// ---- A' fragment-major index (word = half2). Tile = 256 rows x 16 words. ----
__device__ __forceinline__ size_t aidx(int m, int wi, int KPv) {
    int mt = m >> 8, r = m & 255;
    int kt = wi >> 4, c = wi & 15;
    int kk = c >> 3, q = c & 3, kd = (c >> 2) & 1;
    int wq = r >> 6, mi = (r >> 4) & 3, rh = (r >> 3) & 1, g = r & 7;
    int off = ((((kk * 4 + wq) * 4 + mi) * 32 + g * 4 + q) * 4 + kd * 2 + rh);
    return (size_t)(mt * (KPv >> 5) + kt) * 4096 + off;
}

// ---- B' fragment-major index. Tile = 128 cols x 16 words. ----
__device__ __forceinline__ size_t bidx(int n, int k2, int KPv) {
    int nt = n >> 7, nn = n & 127;
    int kt = k2 >> 4, c = k2 & 15;
    int kk = c >> 3, q = c & 3, kd = (c >> 2) & 1;
    int wni = nn >> 5, ni = (nn >> 3) & 3, g = nn & 7;
    int off = (((kk * 4 + wni) * 2 + kd) * 32 + g * 4 + q) * 4 + ni;
    return (size_t)(nt * (KPv >> 5) + kt) * 2048 + off;
}

__device__ __forceinline__ void cp16(uint32_t dst, const void* src) {
    asm volatile("cp.async.cg.shared.global [%0], [%1], 16;" :: "r"(dst), "l"(src));
}

#define MMA16(acc, a, b0, b1) \
    asm volatile("mma.sync.aligned.m16n8k16.row.col.f32.f16.f16.f32 " \
        "{%0,%1,%2,%3},{%4,%5,%6,%7},{%8,%9},{%0,%1,%2,%3};" \
        : "+f"((acc)[0]), "+f"((acc)[1]), "+f"((acc)[2]), "+f"((acc)[3]) \
        : "r"((a)[0]), "r"((a)[1]), "r"((a)[2]), "r"((a)[3]), "r"(b0), "r"(b1))

// ---------------- setup kernels ----------------
__global__ void stats_zero_k(float* __restrict__ stats) {
    int i = blockIdx.x * blockDim.x + threadIdx.x;
    if (i < STATS_TOTAL) stats[i] = 0.f;
}
__global__ void zero_dc_k(float* __restrict__ degd, float* __restrict__ degp,
                          int* __restrict__ cntd, int* __restrict__ cntp) {
    int i = blockIdx.x * blockDim.x + threadIdx.x;
    if (i < ND) { degd[i] = 0.f; cntd[i] = 0; }
    if (i < NP) { degp[i] = 0.f; cntp[i] = 0; }
}
__global__ void degbucket_k(const int* __restrict__ dei, const float* __restrict__ dew,
                            const int* __restrict__ pei, const float* __restrict__ pew,
                            float* __restrict__ degd, float* __restrict__ degp,
                            int* __restrict__ cntd, int* __restrict__ cntp,
                            int* __restrict__ ebufd, int* __restrict__ ebufp) {
    int i = blockIdx.x * blockDim.x + threadIdx.x;
    if (i < ED) {
        int d = dei[ED + i];
        atomicAdd(&degd[d], dew[i]);
        int j = atomicAdd(&cntd[d], 1);
        if (j < CAP_D) ebufd[(size_t)d * CAP_D + j] = i;
    }
    if (i < EP) {
        int d = pei[EP + i];
        atomicAdd(&degp[d], pew[i]);
        int j = atomicAdd(&cntp[d], 1);
        if (j < CAP_P) ebufp[(size_t)d * CAP_P + j] = i;
    }
}

// weight fp16 (hi only) + transpose into B' layout — n-major for coalescing
__global__ void wsplit_bt_k(const float* __restrict__ W, __half* __restrict__ hi,
                            int K, int N, int KPv) {
    long i = (long)blockIdx.x * blockDim.x + threadIdx.x;
    long total = (long)N * (KPv >> 1);
    if (i >= total) return;
    int k2 = (int)(i / N);
    int n = (int)(i % N);
    int k0 = k2 * 2;
    float v0 = (k0 < K) ? W[(size_t)k0 * N + n] : 0.f;
    float v1 = (k0 + 1 < K) ? W[(size_t)(k0 + 1) * N + n] : 0.f;
    ((uint32_t*)hi)[bidx(n, k2, KPv)] = pack2(__float2half_rn(v0), __float2half_rn(v1));
}

// ---- fused GCN aggregate (gather form, inline rsqrt) + split -> A' layout ----
__global__ void __launch_bounds__(256) gcn_gather_split_k(
    const float* __restrict__ X, const float* __restrict__ deg,
    const int* __restrict__ cnt, const int* __restrict__ ebuf,
    const int* __restrict__ ei, const float* __restrict__ ew,
    const int* __restrict__ idx,
    __half* __restrict__ Gh, __half* __restrict__ Gl,
    int K, int KPv, int CAP) {
    __shared__ int   ssrc[CAP_P];
    __shared__ float snrm[CAP_P];
    int b = blockIdx.x;
    int tid = threadIdx.x;
    int dst = idx[b];
    float disd = rsqrtf(deg[dst] + 1.0f);
    int ne = cnt[dst];
    if (ne > CAP) ne = CAP;
    if (tid < ne) {
        int e = ebuf[(size_t)dst * CAP + tid];
        int s = ei[e];
        ssrc[tid] = s;
        snrm[tid] = rsqrtf(deg[s] + 1.0f) * ew[e] * disd;
    }
    __syncthreads();
    float dd = disd * disd;
    const float* xd = X + (size_t)dst * K;
    for (int c0 = tid * 4; c0 < KPv; c0 += 1024) {
        float4 a = make_float4(0.f, 0.f, 0.f, 0.f);
        if (c0 < K) {
            float4 v = *(const float4*)(xd + c0);
            a.x = dd * v.x; a.y = dd * v.y; a.z = dd * v.z; a.w = dd * v.w;
            for (int j = 0; j < ne; j++) {
                const float4 w = *(const float4*)(X + (size_t)ssrc[j] * K + c0);
                float nr = snrm[j];
                a.x += nr * w.x; a.y += nr * w.y; a.z += nr * w.z; a.w += nr * w.w;
            }
        }
        __half h0, l0, h1, l1;
        int wi = c0 >> 1;
        split_h(a.x, h0, l0); split_h(a.y, h1, l1);
        ((uint32_t*)Gh)[aidx(b, wi, KPv)] = pack2(h0, h1);
        ((uint32_t*)Gl)[aidx(b, wi, KPv)] = pack2(l0, l1);
        split_h(a.z, h0, l0); split_h(a.w, h1, l1);
        ((uint32_t*)Gh)[aidx(b, wi + 1, KPv)] = pack2(h0, h1);
        ((uint32_t*)Gl)[aidx(b, wi + 1, KPv)] = pack2(l0, l1);
    }
}

// F0 base cols [0,1324) + pad words [1686,1696) -> A' layout
__global__ void copy_base_split_k(const float* __restrict__ dvecs, const float* __restrict__ pemb,
                                  __half* __restrict__ F0h, __half* __restrict__ F0l) {
    long idx = (long)blockIdx.x * blockDim.x + threadIdx.x;
    long total = (long)BB * 672;
    if (idx >= total) return;
    int b = (int)(idx / 672);
    int j = (int)(idx % 672);
    int wi;
    float v0 = 0.f, v1 = 0.f;
    if (j < 662) {
        wi = j;
        int k0 = j * 2;
        v0 = (k0 < 300) ? dvecs[(size_t)b * 300 + k0] : pemb[(size_t)b * 1024 + (k0 - 300)];
        v1 = (k0 + 1 < 300) ? dvecs[(size_t)b * 300 + k0 + 1] : pemb[(size_t)b * 1024 + (k0 + 1 - 300)];
    } else {
        wi = 1686 + (j - 662);
    }
    __half h0, l0, h1, l1;
    split_h(v0, h0, l0); split_h(v1, h1, l1);
    size_t w = aidx(b, wi, KP_F0);
    ((uint32_t*)F0h)[w] = pack2(h0, h1);
    ((uint32_t*)F0l)[w] = pack2(l0, l1);
}

// BN + leaky -> A'-layout splits (and optional fp32 row-major copy)
template <int WF32>
__global__ void bn_apply_split_k(const float* __restrict__ xin,
                                 const float* __restrict__ st,
                                 const float* __restrict__ g, const float* __restrict__ be,
                                 __half* __restrict__ hi, __half* __restrict__ lo,
                                 float* __restrict__ fout, int cols) {
    long idx = (long)blockIdx.x * blockDim.x + threadIdx.x;
    int nw = cols >> 1;
    long total = (long)BB * nw;
    if (idx >= total) return;
    int m = (int)(idx / nw);
    int wi = (int)(idx % nw);
    int c0 = wi * 2;
    float m0 = st[c0] * (1.f / BB);
    float m1 = st[c0 + 1] * (1.f / BB);
    float rs0 = rsqrtf(st[cols + c0] * (1.f / BB) - m0 * m0 + EPS);
    float rs1 = rsqrtf(st[cols + c0 + 1] * (1.f / BB) - m1 * m1 + EPS);
    float x0 = xin[(size_t)m * cols + c0];
    float x1 = xin[(size_t)m * cols + c0 + 1];
    float v0 = lrelu((x0 - m0) * rs0 * g[c0] + be[c0]);
    float v1 = lrelu((x1 - m1) * rs1 * g[c0 + 1] + be[c0 + 1]);
    __half h0, l0, h1, l1;
    split_h(v0, h0, l0); split_h(v1, h1, l1);
    size_t w = aidx(m, wi, cols);
    ((uint32_t*)hi)[w] = pack2(h0, h1);
    ((uint32_t*)lo)[w] = pack2(l0, l1);
    if (WF32) {
        fout[(size_t)m * cols + c0] = v0;
        fout[(size_t)m * cols + c0 + 1] = v1;
    }
}

// fused head: y[r] = dot(BN(z3[r,:]), W_o2) + b_o2   (warp per row)
__global__ void bn_out_k(const float* __restrict__ z3, const float* __restrict__ st,
                         const float* __restrict__ g, const float* __restrict__ be,
                         const float* __restrict__ W, const float* __restrict__ b2,
                         float* __restrict__ y) {
    int warp = (blockIdx.x * blockDim.x + threadIdx.x) >> 5;
    int lane = threadIdx.x & 31;
    if (warp >= BB) return;
    float s = 0.f;
    #pragma unroll
    for (int j = 0; j < 8; j++) {
        int c = lane + 32 * j;
        float m = st[c] * (1.f / BB);
        float rs = rsqrtf(st[256 + c] * (1.f / BB) - m * m + EPS);
        float v = (z3[(size_t)warp * 256 + c] - m) * rs * g[c] + be[c];
        s += v * W[c];
    }
    #pragma unroll
    for (int off = 16; off; off >>= 1) s += __shfl_down_sync(0xffffffffu, s, off);
    if (lane == 0) y[warp] = s + b2[0];
}

// ---------------- fragment-major 2-pass fp16-split GEMM ----------------
#define TILE_WORDS 10240         // Ah 4096 | Al 4096 | Bh 2048
#define FG_STG 3
#define FG_SMEM (FG_STG * TILE_WORDS * 4)   // 122880 bytes

template <int ACT, int OUTS, int STATS>
__global__ void __launch_bounds__(512, 1) fgemm_k(
    const uint32_t* __restrict__ Ahw, const uint32_t* __restrict__ Alw,
    const uint32_t* __restrict__ Bhw,
    const float* __restrict__ bias,
    float* __restrict__ Cf, __half* __restrict__ Chi, __half* __restrict__ Clo,
    float* __restrict__ stp,
    int KPv, int ldc, int KPc, int coloff) {
    extern __shared__ uint32_t smw[];
    uint32_t smb = (uint32_t)__cvta_generic_to_shared(smw);
    const int tid = threadIdx.x;
    const int warp = tid >> 5, lane = tid & 31;
    const int wq = warp >> 2, wni = warp & 3;
    const int g = lane >> 2, q = lane & 3;
    const int bn0 = blockIdx.x * 128;
    const int bm0 = blockIdx.y * 256;
    const int KT = KPv >> 5;
    const size_t abase = (size_t)blockIdx.y * KT * 4096;
    const size_t bbase = (size_t)blockIdx.x * KT * 2048;

    auto issue = [&](int t) {
        uint32_t s = smb + (uint32_t)(t % FG_STG) * (TILE_WORDS * 4);
        const uint32_t* ga  = Ahw + abase + (size_t)t * 4096;
        const uint32_t* gal = Alw + abase + (size_t)t * 4096;
        const uint32_t* gb  = Bhw + bbase + (size_t)t * 2048;
        #pragma unroll
        for (int j = 0; j < 5; j++) {
            int ch = j * 512 + tid;
            const uint32_t* src;
            if (ch < 1024)      src = ga  + ch * 4;
            else if (ch < 2048) src = gal + (ch - 1024) * 4;
            else                src = gb  + (ch - 2048) * 4;
            cp16(s + ch * 16, src);
        }
        asm volatile("cp.async.commit_group;");
    };

    float acc[4][4][4];
    #pragma unroll
    for (int mi = 0; mi < 4; mi++)
        #pragma unroll
        for (int ni = 0; ni < 4; ni++)
            #pragma unroll
            for (int r = 0; r < 4; r++) acc[mi][ni][r] = 0.f;

    issue(0);
    issue(1);

    for (int t = 0; t < KT; t++) {
        if (t + 1 < KT) asm volatile("cp.async.wait_group 1;");
        else            asm volatile("cp.async.wait_group 0;");
        __syncthreads();
        if (t + 2 < KT) issue(t + 2);

        const uint32_t* st  = smw + (t % FG_STG) * TILE_WORDS;
        const uint32_t* sAh = st;
        const uint32_t* sAl = st + 4096;
        const uint32_t* sBh = st + 8192;

        #pragma unroll
        for (int kk = 0; kk < 2; kk++) {
            uint32_t ah[4][4], bb[2][4];
            #pragma unroll
            for (int mi = 0; mi < 4; mi++)
                *(uint4*)ah[mi] = *(const uint4*)(sAh + (((kk * 4 + wq) * 4 + mi) * 32 + lane) * 4);
            #pragma unroll
            for (int kd = 0; kd < 2; kd++)
                *(uint4*)bb[kd] = *(const uint4*)(sBh + (((kk * 4 + wni) * 2 + kd) * 32 + lane) * 4);
            // pass 1: Ahi*Bhi
            #pragma unroll
            for (int ni = 0; ni < 4; ni++)
                #pragma unroll
                for (int mi = 0; mi < 4; mi++)
                    MMA16(acc[mi][ni], ah[mi], bb[0][ni], bb[1][ni]);
            // pass 2: Alo*Bhi
            {
                uint32_t al[4][4];
                #pragma unroll
                for (int mi = 0; mi < 4; mi++)
                    *(uint4*)al[mi] = *(const uint4*)(sAl + (((kk * 4 + wq) * 4 + mi) * 32 + lane) * 4);
                #pragma unroll
                for (int ni = 0; ni < 4; ni++)
                    #pragma unroll
                    for (int mi = 0; mi < 4; mi++)
                        MMA16(acc[mi][ni], al[mi], bb[0][ni], bb[1][ni]);
            }
        }
    }

    // epilogue (+ optional fused BN column stats)
    float cs[4][2], cq[4][2];
    if (STATS) {
        #pragma unroll
        for (int ni = 0; ni < 4; ni++) {
            cs[ni][0] = cs[ni][1] = 0.f;
            cq[ni][0] = cq[ni][1] = 0.f;
        }
    }
    #pragma unroll
    for (int mi = 0; mi < 4; mi++) {
        #pragma unroll
        for (int ni = 0; ni < 4; ni++) {
            int r0 = bm0 + wq * 64 + mi * 16 + g;
            int cg = bn0 + wni * 32 + ni * 8 + 2 * q;
            float v0 = acc[mi][ni][0] + bias[cg];
            float v1 = acc[mi][ni][1] + bias[cg + 1];
            float v2 = acc[mi][ni][2] + bias[cg];
            float v3 = acc[mi][ni][3] + bias[cg + 1];
            if (ACT == 1) { v0 = lrelu(v0); v1 = lrelu(v1); v2 = lrelu(v2); v3 = lrelu(v3); }
            if (STATS) {
                cs[ni][0] += v0 + v2; cs[ni][1] += v1 + v3;
                cq[ni][0] += v0 * v0 + v2 * v2;
                cq[ni][1] += v1 * v1 + v3 * v3;
            }
            if (OUTS == 1) {
                __half h0, l0, h1, l1;
                int wi = (coloff + cg) >> 1;
                split_h(v0, h0, l0); split_h(v1, h1, l1);
                size_t w = aidx(r0, wi, KPc);
                ((uint32_t*)Chi)[w] = pack2(h0, h1);
                ((uint32_t*)Clo)[w] = pack2(l0, l1);
                split_h(v2, h0, l0); split_h(v3, h1, l1);
                w = aidx(r0 + 8, wi, KPc);
                ((uint32_t*)Chi)[w] = pack2(h0, h1);
                ((uint32_t*)Clo)[w] = pack2(l0, l1);
            } else {
                float2 a; a.x = v0; a.y = v1;
                float2 b; b.x = v2; b.y = v3;
                *(float2*)(Cf + (size_t)r0 * ldc + cg) = a;
                *(float2*)(Cf + (size_t)(r0 + 8) * ldc + cg) = b;
            }
        }
    }
    if (STATS) {
        #pragma unroll
        for (int ni = 0; ni < 4; ni++) {
            #pragma unroll
            for (int j = 0; j < 2; j++) {
                #pragma unroll
                for (int off = 16; off >= 4; off >>= 1) {
                    cs[ni][j] += __shfl_down_sync(0xffffffffu, cs[ni][j], off);
                    cq[ni][j] += __shfl_down_sync(0xffffffffu, cq[ni][j], off);
                }
            }
        }
        if (lane < 4) {
            #pragma unroll
            for (int ni = 0; ni < 4; ni++) {
                int cg = bn0 + wni * 32 + ni * 8 + 2 * q;
                atomicAdd(&stp[cg], cs[ni][0]);
                atomicAdd(&stp[cg + 1], cs[ni][1]);
                atomicAdd(&stp[ldc + cg], cq[ni][0]);
                atomicAdd(&stp[ldc + cg + 1], cq[ni][1]);
            }
        }
    }
}

// ---------------- launch ----------------
extern "C" void kernel_launch(void* const* d_in, const int* in_sizes, int n_in,
                              void* d_out, int out_size) {
    (void)in_sizes; (void)n_in; (void)out_size;
    const int*   d_index  = (const int*)d_in[0];
    const int*   p_index  = (const int*)d_in[1];
    const float* d_vecs   = (const float*)d_in[2];
    const float* p_emb    = (const float*)d_in[3];
    const float* d_ecfps  = (const float*)d_in[4];
    const int*   d_ei     = (const int*)d_in[5];
    const float* d_ew     = (const float*)d_in[6];
    const float* p_gos    = (const float*)d_in[7];
    const int*   p_ei     = (const int*)d_in[8];
    const float* p_ew     = (const float*)d_in[9];
    const float* W_dg     = (const float*)d_in[10];
    const float* b_dg     = (const float*)d_in[11];
    const float* W_pg     = (const float*)d_in[12];
    const float* b_pg     = (const float*)d_in[13];
    const float* W_e1     = (const float*)d_in[14];
    const float* b_e1     = (const float*)d_in[15];
    const float* g_e1     = (const float*)d_in[16];
    const float* be_e1    = (const float*)d_in[17];
    const float* W_e2     = (const float*)d_in[18];
    const float* b_e2     = (const float*)d_in[19];
    const float* g_e2     = (const float*)d_in[20];
    const float* be_e2    = (const float*)d_in[21];
    const float* W_o1     = (const float*)d_in[22];
    const float* b_o1     = (const float*)d_in[23];
    const float* g_o      = (const float*)d_in[24];
    const float* be_o     = (const float*)d_in[25];
    const float* W_o2     = (const float*)d_in[26];
    const float* b_o2     = (const float*)d_in[27];

    float* out = (float*)d_out;
    float* y_out = out;
    float* feat_out = out + BB;

    float *degd, *degp, *z1, *z2, *z3, *stats;
    int *cntd, *cntp, *ebufd, *ebufp;
    __half *Gdh, *Gdl, *Gph, *Gpl, *F0h, *F0l, *Z1h, *Z1l, *Fh, *Fl;
    __half *Wdgh, *Wpgh, *We1h, *We2h, *Wo1h;
    cudaGetSymbolAddress((void**)&degd, g_degd);
    cudaGetSymbolAddress((void**)&degp, g_degp);
    cudaGetSymbolAddress((void**)&cntd, g_cntd);
    cudaGetSymbolAddress((void**)&cntp, g_cntp);
    cudaGetSymbolAddress((void**)&ebufd, g_ebufd);
    cudaGetSymbolAddress((void**)&ebufp, g_ebufp);
    cudaGetSymbolAddress((void**)&z1, g_z1);
    cudaGetSymbolAddress((void**)&z2, g_z2);
    cudaGetSymbolAddress((void**)&z3, g_z3);
    cudaGetSymbolAddress((void**)&stats, g_stats);
    cudaGetSymbolAddress((void**)&Gdh, g_Gdh); cudaGetSymbolAddress((void**)&Gdl, g_Gdl);
    cudaGetSymbolAddress((void**)&Gph, g_Gph); cudaGetSymbolAddress((void**)&Gpl, g_Gpl);
    cudaGetSymbolAddress((void**)&F0h, g_F0h); cudaGetSymbolAddress((void**)&F0l, g_F0l);
    cudaGetSymbolAddress((void**)&Z1h, g_Z1h); cudaGetSymbolAddress((void**)&Z1l, g_Z1l);
    cudaGetSymbolAddress((void**)&Fh, g_Fh);   cudaGetSymbolAddress((void**)&Fl, g_Fl);
    cudaGetSymbolAddress((void**)&Wdgh, g_Wdgh);
    cudaGetSymbolAddress((void**)&Wpgh, g_Wpgh);
    cudaGetSymbolAddress((void**)&We1h, g_We1h);
    cudaGetSymbolAddress((void**)&We2h, g_We2h);
    cudaGetSymbolAddress((void**)&Wo1h, g_Wo1h);

    float* stats1 = stats;          // e1: 2048 cols
    float* stats2 = stats + 4096;   // e2: 1024 cols
    float* stats3 = stats + 6144;   // o:  256 cols

    static cudaStream_t s1 = nullptr, s2 = nullptr;
    static cudaEvent_t evA = nullptr, evWd = nullptr, evDeg = nullptr, evPga = nullptr,
                       evGd = nullptr, evC = nullptr, evZ = nullptr, evPG = nullptr;
    static bool attr_done = false;
    if (!attr_done) {
        cudaFuncSetAttribute(fgemm_k<1, 1, 0>, cudaFuncAttributeMaxDynamicSharedMemorySize, FG_SMEM);
        cudaFuncSetAttribute(fgemm_k<0, 0, 1>, cudaFuncAttributeMaxDynamicSharedMemorySize, FG_SMEM);
        cudaFuncSetAttribute(fgemm_k<1, 0, 1>, cudaFuncAttributeMaxDynamicSharedMemorySize, FG_SMEM);
        cudaStreamCreateWithFlags(&s1, cudaStreamNonBlocking);
        cudaStreamCreateWithFlags(&s2, cudaStreamNonBlocking);
        cudaEventCreateWithFlags(&evA, cudaEventDisableTiming);
        cudaEventCreateWithFlags(&evWd, cudaEventDisableTiming);
        cudaEventCreateWithFlags(&evDeg, cudaEventDisableTiming);
        cudaEventCreateWithFlags(&evPga, cudaEventDisableTiming);
        cudaEventCreateWithFlags(&evGd, cudaEventDisableTiming);
        cudaEventCreateWithFlags(&evC, cudaEventDisableTiming);
        cudaEventCreateWithFlags(&evZ, cudaEventDisableTiming);
        cudaEventCreateWithFlags(&evPG, cudaEventDisableTiming);
        attr_done = true;
    }

    cudaEventRecord(evA, 0);
    cudaStreamWaitEvent(s1, evA, 0);
    cudaStreamWaitEvent(s2, evA, 0);

    // ---- s1: p-branch chain: Wpg split -> (after buckets) gather_p -> p-GEMM ----
    wsplit_bt_k<<<((long)1024 * (KP_GP / 2) + 255) / 256, 256, 0, s1>>>(W_pg, Wpgh, 2812, 1024, KP_GP);

    // ---- s2: d-weights + remaining prep ----
    wsplit_bt_k<<<((long)1024 * (KP_GD / 2) + 255) / 256, 256, 0, s2>>>(W_dg, Wdgh, 1024, 1024, KP_GD);
    cudaEventRecord(evWd, s2);
    copy_base_split_k<<<((long)BB * 672 + 255) / 256, 256, 0, s2>>>(d_vecs, p_emb, F0h, F0l);
    wsplit_bt_k<<<((long)2048 * (KP_F0 / 2) + 255) / 256, 256, 0, s2>>>(W_e1, We1h, 3372, 2048, KP_F0);
    wsplit_bt_k<<<((long)1024 * (KP_Z1 / 2) + 255) / 256, 256, 0, s2>>>(W_e2, We2h, 2048, 1024, KP_Z1);
    wsplit_bt_k<<<((long)256 * (KP_F / 2) + 255) / 256, 256, 0, s2>>>(W_o1, Wo1h, 1024, 256, KP_F);
    cudaEventRecord(evC, s2);

    // ---- main: stats zero + edge buckets ----
    stats_zero_k<<<(STATS_TOTAL + 255) / 256, 256>>>(stats);
    degbucket_k<<<(ED + 255) / 256, 256>>>(d_ei, d_ew, p_ei, p_ew, degd, degp,
                                           cntd, cntp, ebufd, ebufp);
    cudaEventRecord(evDeg, 0);

    // ---- s1: gather_p then p-GEMM (runs concurrently with main's gather_d + d-GEMM) ----
    cudaStreamWaitEvent(s1, evDeg, 0);
    gcn_gather_split_k<<<BB, 256, 0, s1>>>(p_gos, degp, cntp, ebufp, p_ei, p_ew, p_index,
                                           Gph, Gpl, 2812, KP_GP, CAP_P);
    cudaEventRecord(evPga, s1);
    fgemm_k<1, 1, 0><<<dim3(8, 16), 512, FG_SMEM, s1>>>((const uint32_t*)Gph, (const uint32_t*)Gpl,
        (const uint32_t*)Wpgh, b_pg, nullptr, F0h, F0l, nullptr, KP_GP, 0, KP_F0, 2348);
    cudaEventRecord(evPG, s1);

    // ---- main: gather_d then d-GEMM (concurrent with s1's p-GEMM) ----
    gcn_gather_split_k<<<BB, 256>>>(d_ecfps, degd, cntd, ebufd, d_ei, d_ew, d_index,
                                    Gdh, Gdl, 1024, KP_GD, CAP_D);
    cudaEventRecord(evGd, 0);
    cudaStreamWaitEvent(0, evWd, 0);
    fgemm_k<1, 1, 0><<<dim3(8, 16), 512, FG_SMEM>>>((const uint32_t*)Gdh, (const uint32_t*)Gdl,
        (const uint32_t*)Wdgh, b_dg, nullptr, F0h, F0l, nullptr, KP_GD, 0, KP_F0, 1324);

    // ---- s2 tail: restore deg/cnt to zero (after both gathers) ----
    cudaStreamWaitEvent(s2, evGd, 0);
    cudaStreamWaitEvent(s2, evPga, 0);
    zero_dc_k<<<(ND + 255) / 256, 256, 0, s2>>>(degd, degp, cntd, cntp);
    cudaEventRecord(evZ, s2);

    // ---- e1 (needs p-GEMM from s1, copy_base + We1 from s2) ----
    cudaStreamWaitEvent(0, evPG, 0);
    cudaStreamWaitEvent(0, evC, 0);
    fgemm_k<0, 0, 1><<<dim3(16, 16), 512, FG_SMEM>>>((const uint32_t*)F0h, (const uint32_t*)F0l,
        (const uint32_t*)We1h, b_e1, z1, nullptr, nullptr, stats1, KP_F0, 2048, 0, 0);
    bn_apply_split_k<0><<<((long)BB * 1024 + 255) / 256, 256>>>(z1, stats1, g_e1, be_e1,
        Z1h, Z1l, nullptr, 2048);

    // e2 -> feature (d_out)
    fgemm_k<0, 0, 1><<<dim3(8, 16), 512, FG_SMEM>>>((const uint32_t*)Z1h, (const uint32_t*)Z1l,
        (const uint32_t*)We2h, b_e2, z2, nullptr, nullptr, stats2, KP_Z1, 1024, 0, 0);
    bn_apply_split_k<1><<<((long)BB * 512 + 255) / 256, 256>>>(z2, stats2, g_e2, be_e2,
        Fh, Fl, feat_out, 1024);

    // output head: GEMM (leaky+stats fused) then fused BN+dot
    fgemm_k<1, 0, 1><<<dim3(2, 16), 512, FG_SMEM>>>((const uint32_t*)Fh, (const uint32_t*)Fl,
        (const uint32_t*)Wo1h, b_o1, z3, nullptr, nullptr, stats3, KP_F, 256, 0, 0);
    // join s2's zero_dc tail before the final kernel (all side-stream work joined)
    cudaStreamWaitEvent(0, evZ, 0);
    bn_out_k<<<(BB * 32 + 255) / 256, 256>>>(z3, stats3, g_o, be_o, W_o2, b_o2, y_out);
}

// round 17
// speedup vs baseline: 1.0073x; 1.0073x over previous
#include <cuda_runtime.h>
#include <cuda_fp16.h>
#include <cstdint>

// ---------------- problem constants ----------------
#define ND 50000
#define NP 20000
#define ED 65536
#define EP 65536
#define BB 4096
#define EPS 1e-5f
#define CAP_D 32
#define CAP_P 64

// padded K dims (multiples of 32)
#define KP_GD 1024
#define KP_GP 2816
#define KP_F0 3392
#define KP_Z1 2048
#define KP_F  1024

// ---------------- scratch (zero-initialized at module load; re-zeroed at end of each run) ----------------
__device__ float g_degd[ND];
__device__ float g_degp[NP];
__device__ int   g_cntd[ND];
__device__ int   g_cntp[NP];
__device__ int   g_ebufd[(size_t)ND * CAP_D];
__device__ int   g_ebufp[(size_t)NP * CAP_P];
__device__ float g_z1[(size_t)BB * 2048];
__device__ float g_z2[(size_t)BB * 1024];
__device__ float g_z3[(size_t)BB * 256];
#define STATS_TOTAL 6656
__device__ float g_stats[STATS_TOTAL];

// A-side fp16 hi/lo, fragment-major A' layout (tile 256m x 32k)
__device__ __half g_Gdh[(size_t)BB * KP_GD], g_Gdl[(size_t)BB * KP_GD];
__device__ __half g_Gph[(size_t)BB * KP_GP], g_Gpl[(size_t)BB * KP_GP];
__device__ __half g_F0h[(size_t)BB * KP_F0], g_F0l[(size_t)BB * KP_F0];
__device__ __half g_Z1h[(size_t)BB * KP_Z1], g_Z1l[(size_t)BB * KP_Z1];
__device__ __half g_Fh[(size_t)BB * KP_F],   g_Fl[(size_t)BB * KP_F];
// B-side fp16 hi only, fragment-major B' layout (tile 128n x 32k)
__device__ __half g_Wdgh[(size_t)KP_GD * 1024];
__device__ __half g_Wpgh[(size_t)KP_GP * 1024];
__device__ __half g_We1h[(size_t)KP_F0 * 2048];
__device__ __half g_We2h[(size_t)KP_Z1 * 1024];
__device__ __half g_Wo1h[(size_t)KP_F * 256];

__device__ __forceinline__ float lrelu(float x) { return x >= 0.f ? x : 0.01f * x; }

__device__ __forceinline__ void split_h(float f, __half& hi, __half& lo) {
    hi = __float2half_rn(f);
    lo = __float2half_rn(f - __half2float(hi));
}

__device__ __forceinline__ uint32_t pack2(__half a, __half b) {
    __half2 h = __halves2half2(a, b);
    return *reinterpret_cast<uint32_t*>(&h);
}

// ---- A' fragment-major index (word = half2). Tile = 256 rows x 16 words. ----
__device__ __forceinline__ size_t aidx(int m, int wi, int KPv) {
    int mt = m >> 8, r = m & 255;
    int kt = wi >> 4, c = wi & 15;
    int kk = c >> 3, q = c & 3, kd = (c >> 2) & 1;
    int wq = r >> 6, mi = (r >> 4) & 3, rh = (r >> 3) & 1, g = r & 7;
    int off = ((((kk * 4 + wq) * 4 + mi) * 32 + g * 4 + q) * 4 + kd * 2 + rh);
    return (size_t)(mt * (KPv >> 5) + kt) * 4096 + off;
}

// ---- B' fragment-major index. Tile = 128 cols x 16 words. ----
__device__ __forceinline__ size_t bidx(int n, int k2, int KPv) {
    int nt = n >> 7, nn = n & 127;
    int kt = k2 >> 4, c = k2 & 15;
    int kk = c >> 3, q = c & 3, kd = (c >> 2) & 1;
    int wni = nn >> 5, ni = (nn >> 3) & 3, g = nn & 7;
    int off = (((kk * 4 + wni) * 2 + kd) * 32 + g * 4 + q) * 4 + ni;
    return (size_t)(nt * (KPv >> 5) + kt) * 2048 + off;
}

__device__ __forceinline__ void cp16(uint32_t dst, const void* src) {
    asm volatile("cp.async.cg.shared.global [%0], [%1], 16;" :: "r"(dst), "l"(src));
}

#define MMA16(acc, a, b0, b1) \
    asm volatile("mma.sync.aligned.m16n8k16.row.col.f32.f16.f16.f32 " \
        "{%0,%1,%2,%3},{%4,%5,%6,%7},{%8,%9},{%0,%1,%2,%3};" \
        : "+f"((acc)[0]), "+f"((acc)[1]), "+f"((acc)[2]), "+f"((acc)[3]) \
        : "r"((a)[0]), "r"((a)[1]), "r"((a)[2]), "r"((a)[3]), "r"(b0), "r"(b1))

// ---------------- setup kernels ----------------
// end-of-run cleanup: restore deg/cnt to zero for the next replay
__global__ void zero_dc_k(float* __restrict__ degd, float* __restrict__ degp,
                          int* __restrict__ cntd, int* __restrict__ cntp) {
    int i = blockIdx.x * blockDim.x + threadIdx.x;
    if (i < ND) { degd[i] = 0.f; cntd[i] = 0; }
    if (i < NP) { degp[i] = 0.f; cntp[i] = 0; }
}
// fused: BN-stats zeroing + degree accumulate + per-dst edge bucket fill
__global__ void degbucket_k(const int* __restrict__ dei, const float* __restrict__ dew,
                            const int* __restrict__ pei, const float* __restrict__ pew,
                            float* __restrict__ degd, float* __restrict__ degp,
                            int* __restrict__ cntd, int* __restrict__ cntp,
                            int* __restrict__ ebufd, int* __restrict__ ebufp,
                            float* __restrict__ stats) {
    int i = blockIdx.x * blockDim.x + threadIdx.x;
    if (i < STATS_TOTAL) stats[i] = 0.f;
    if (i < ED) {
        int d = dei[ED + i];
        atomicAdd(&degd[d], dew[i]);
        int j = atomicAdd(&cntd[d], 1);
        if (j < CAP_D) ebufd[(size_t)d * CAP_D + j] = i;
    }
    if (i < EP) {
        int d = pei[EP + i];
        atomicAdd(&degp[d], pew[i]);
        int j = atomicAdd(&cntp[d], 1);
        if (j < CAP_P) ebufp[(size_t)d * CAP_P + j] = i;
    }
}

// weight fp16 (hi only) + transpose into B' layout — n-major for coalescing
__global__ void wsplit_bt_k(const float* __restrict__ W, __half* __restrict__ hi,
                            int K, int N, int KPv) {
    long i = (long)blockIdx.x * blockDim.x + threadIdx.x;
    long total = (long)N * (KPv >> 1);
    if (i >= total) return;
    int k2 = (int)(i / N);
    int n = (int)(i % N);
    int k0 = k2 * 2;
    float v0 = (k0 < K) ? W[(size_t)k0 * N + n] : 0.f;
    float v1 = (k0 + 1 < K) ? W[(size_t)(k0 + 1) * N + n] : 0.f;
    ((uint32_t*)hi)[bidx(n, k2, KPv)] = pack2(__float2half_rn(v0), __float2half_rn(v1));
}

// ---- fused GCN aggregate (gather form, inline rsqrt) + split -> A' layout ----
__global__ void __launch_bounds__(256) gcn_gather_split_k(
    const float* __restrict__ X, const float* __restrict__ deg,
    const int* __restrict__ cnt, const int* __restrict__ ebuf,
    const int* __restrict__ ei, const float* __restrict__ ew,
    const int* __restrict__ idx,
    __half* __restrict__ Gh, __half* __restrict__ Gl,
    int K, int KPv, int CAP) {
    __shared__ int   ssrc[CAP_P];
    __shared__ float snrm[CAP_P];
    int b = blockIdx.x;
    int tid = threadIdx.x;
    int dst = idx[b];
    float disd = rsqrtf(deg[dst] + 1.0f);
    int ne = cnt[dst];
    if (ne > CAP) ne = CAP;
    if (tid < ne) {
        int e = ebuf[(size_t)dst * CAP + tid];
        int s = ei[e];
        ssrc[tid] = s;
        snrm[tid] = rsqrtf(deg[s] + 1.0f) * ew[e] * disd;
    }
    __syncthreads();
    float dd = disd * disd;
    const float* xd = X + (size_t)dst * K;
    for (int c0 = tid * 4; c0 < KPv; c0 += 1024) {
        float4 a = make_float4(0.f, 0.f, 0.f, 0.f);
        if (c0 < K) {
            float4 v = *(const float4*)(xd + c0);
            a.x = dd * v.x; a.y = dd * v.y; a.z = dd * v.z; a.w = dd * v.w;
            for (int j = 0; j < ne; j++) {
                const float4 w = *(const float4*)(X + (size_t)ssrc[j] * K + c0);
                float nr = snrm[j];
                a.x += nr * w.x; a.y += nr * w.y; a.z += nr * w.z; a.w += nr * w.w;
            }
        }
        __half h0, l0, h1, l1;
        int wi = c0 >> 1;
        split_h(a.x, h0, l0); split_h(a.y, h1, l1);
        ((uint32_t*)Gh)[aidx(b, wi, KPv)] = pack2(h0, h1);
        ((uint32_t*)Gl)[aidx(b, wi, KPv)] = pack2(l0, l1);
        split_h(a.z, h0, l0); split_h(a.w, h1, l1);
        ((uint32_t*)Gh)[aidx(b, wi + 1, KPv)] = pack2(h0, h1);
        ((uint32_t*)Gl)[aidx(b, wi + 1, KPv)] = pack2(l0, l1);
    }
}

// F0 base cols [0,1324) + pad words [1686,1696) -> A' layout
__global__ void copy_base_split_k(const float* __restrict__ dvecs, const float* __restrict__ pemb,
                                  __half* __restrict__ F0h, __half* __restrict__ F0l) {
    long idx = (long)blockIdx.x * blockDim.x + threadIdx.x;
    long total = (long)BB * 672;
    if (idx >= total) return;
    int b = (int)(idx / 672);
    int j = (int)(idx % 672);
    int wi;
    float v0 = 0.f, v1 = 0.f;
    if (j < 662) {
        wi = j;
        int k0 = j * 2;
        v0 = (k0 < 300) ? dvecs[(size_t)b * 300 + k0] : pemb[(size_t)b * 1024 + (k0 - 300)];
        v1 = (k0 + 1 < 300) ? dvecs[(size_t)b * 300 + k0 + 1] : pemb[(size_t)b * 1024 + (k0 + 1 - 300)];
    } else {
        wi = 1686 + (j - 662);
    }
    __half h0, l0, h1, l1;
    split_h(v0, h0, l0); split_h(v1, h1, l1);
    size_t w = aidx(b, wi, KP_F0);
    ((uint32_t*)F0h)[w] = pack2(h0, h1);
    ((uint32_t*)F0l)[w] = pack2(l0, l1);
}

// BN + leaky -> A'-layout splits (and optional fp32 row-major copy)
template <int WF32>
__global__ void bn_apply_split_k(const float* __restrict__ xin,
                                 const float* __restrict__ st,
                                 const float* __restrict__ g, const float* __restrict__ be,
                                 __half* __restrict__ hi, __half* __restrict__ lo,
                                 float* __restrict__ fout, int cols) {
    long idx = (long)blockIdx.x * blockDim.x + threadIdx.x;
    int nw = cols >> 1;
    long total = (long)BB * nw;
    if (idx >= total) return;
    int m = (int)(idx / nw);
    int wi = (int)(idx % nw);
    int c0 = wi * 2;
    float m0 = st[c0] * (1.f / BB);
    float m1 = st[c0 + 1] * (1.f / BB);
    float rs0 = rsqrtf(st[cols + c0] * (1.f / BB) - m0 * m0 + EPS);
    float rs1 = rsqrtf(st[cols + c0 + 1] * (1.f / BB) - m1 * m1 + EPS);
    float x0 = xin[(size_t)m * cols + c0];
    float x1 = xin[(size_t)m * cols + c0 + 1];
    float v0 = lrelu((x0 - m0) * rs0 * g[c0] + be[c0]);
    float v1 = lrelu((x1 - m1) * rs1 * g[c0 + 1] + be[c0 + 1]);
    __half h0, l0, h1, l1;
    split_h(v0, h0, l0); split_h(v1, h1, l1);
    size_t w = aidx(m, wi, cols);
    ((uint32_t*)hi)[w] = pack2(h0, h1);
    ((uint32_t*)lo)[w] = pack2(l0, l1);
    if (WF32) {
        fout[(size_t)m * cols + c0] = v0;
        fout[(size_t)m * cols + c0 + 1] = v1;
    }
}

// fused head: y[r] = dot(BN(z3[r,:]), W_o2) + b_o2   (warp per row)
__global__ void bn_out_k(const float* __restrict__ z3, const float* __restrict__ st,
                         const float* __restrict__ g, const float* __restrict__ be,
                         const float* __restrict__ W, const float* __restrict__ b2,
                         float* __restrict__ y) {
    int warp = (blockIdx.x * blockDim.x + threadIdx.x) >> 5;
    int lane = threadIdx.x & 31;
    if (warp >= BB) return;
    float s = 0.f;
    #pragma unroll
    for (int j = 0; j < 8; j++) {
        int c = lane + 32 * j;
        float m = st[c] * (1.f / BB);
        float rs = rsqrtf(st[256 + c] * (1.f / BB) - m * m + EPS);
        float v = (z3[(size_t)warp * 256 + c] - m) * rs * g[c] + be[c];
        s += v * W[c];
    }
    #pragma unroll
    for (int off = 16; off; off >>= 1) s += __shfl_down_sync(0xffffffffu, s, off);
    if (lane == 0) y[warp] = s + b2[0];
}

// ---------------- fragment-major 2-pass fp16-split GEMM ----------------
#define TILE_WORDS 10240         // Ah 4096 | Al 4096 | Bh 2048
#define FG_STG 3
#define FG_SMEM (FG_STG * TILE_WORDS * 4)   // 122880 bytes

template <int ACT, int OUTS, int STATS>
__global__ void __launch_bounds__(512, 1) fgemm_k(
    const uint32_t* __restrict__ Ahw, const uint32_t* __restrict__ Alw,
    const uint32_t* __restrict__ Bhw,
    const float* __restrict__ bias,
    float* __restrict__ Cf, __half* __restrict__ Chi, __half* __restrict__ Clo,
    float* __restrict__ stp,
    int KPv, int ldc, int KPc, int coloff) {
    extern __shared__ uint32_t smw[];
    uint32_t smb = (uint32_t)__cvta_generic_to_shared(smw);
    const int tid = threadIdx.x;
    const int warp = tid >> 5, lane = tid & 31;
    const int wq = warp >> 2, wni = warp & 3;
    const int g = lane >> 2, q = lane & 3;
    const int bn0 = blockIdx.x * 128;
    const int bm0 = blockIdx.y * 256;
    const int KT = KPv >> 5;
    const size_t abase = (size_t)blockIdx.y * KT * 4096;
    const size_t bbase = (size_t)blockIdx.x * KT * 2048;

    auto issue = [&](int t) {
        uint32_t s = smb + (uint32_t)(t % FG_STG) * (TILE_WORDS * 4);
        const uint32_t* ga  = Ahw + abase + (size_t)t * 4096;
        const uint32_t* gal = Alw + abase + (size_t)t * 4096;
        const uint32_t* gb  = Bhw + bbase + (size_t)t * 2048;
        #pragma unroll
        for (int j = 0; j < 5; j++) {
            int ch = j * 512 + tid;
            const uint32_t* src;
            if (ch < 1024)      src = ga  + ch * 4;
            else if (ch < 2048) src = gal + (ch - 1024) * 4;
            else                src = gb  + (ch - 2048) * 4;
            cp16(s + ch * 16, src);
        }
        asm volatile("cp.async.commit_group;");
    };

    float acc[4][4][4];
    #pragma unroll
    for (int mi = 0; mi < 4; mi++)
        #pragma unroll
        for (int ni = 0; ni < 4; ni++)
            #pragma unroll
            for (int r = 0; r < 4; r++) acc[mi][ni][r] = 0.f;

    issue(0);
    issue(1);

    for (int t = 0; t < KT; t++) {
        if (t + 1 < KT) asm volatile("cp.async.wait_group 1;");
        else            asm volatile("cp.async.wait_group 0;");
        __syncthreads();
        if (t + 2 < KT) issue(t + 2);

        const uint32_t* st  = smw + (t % FG_STG) * TILE_WORDS;
        const uint32_t* sAh = st;
        const uint32_t* sAl = st + 4096;
        const uint32_t* sBh = st + 8192;

        #pragma unroll
        for (int kk = 0; kk < 2; kk++) {
            uint32_t ah[4][4], bb[2][4];
            #pragma unroll
            for (int mi = 0; mi < 4; mi++)
                *(uint4*)ah[mi] = *(const uint4*)(sAh + (((kk * 4 + wq) * 4 + mi) * 32 + lane) * 4);
            #pragma unroll
            for (int kd = 0; kd < 2; kd++)
                *(uint4*)bb[kd] = *(const uint4*)(sBh + (((kk * 4 + wni) * 2 + kd) * 32 + lane) * 4);
            // pass 1: Ahi*Bhi
            #pragma unroll
            for (int ni = 0; ni < 4; ni++)
                #pragma unroll
                for (int mi = 0; mi < 4; mi++)
                    MMA16(acc[mi][ni], ah[mi], bb[0][ni], bb[1][ni]);
            // pass 2: Alo*Bhi
            {
                uint32_t al[4][4];
                #pragma unroll
                for (int mi = 0; mi < 4; mi++)
                    *(uint4*)al[mi] = *(const uint4*)(sAl + (((kk * 4 + wq) * 4 + mi) * 32 + lane) * 4);
                #pragma unroll
                for (int ni = 0; ni < 4; ni++)
                    #pragma unroll
                    for (int mi = 0; mi < 4; mi++)
                        MMA16(acc[mi][ni], al[mi], bb[0][ni], bb[1][ni]);
            }
        }
    }

    // epilogue (+ optional fused BN column stats)
    float cs[4][2], cq[4][2];
    if (STATS) {
        #pragma unroll
        for (int ni = 0; ni < 4; ni++) {
            cs[ni][0] = cs[ni][1] = 0.f;
            cq[ni][0] = cq[ni][1] = 0.f;
        }
    }
    #pragma unroll
    for (int mi = 0; mi < 4; mi++) {
        #pragma unroll
        for (int ni = 0; ni < 4; ni++) {
            int r0 = bm0 + wq * 64 + mi * 16 + g;
            int cg = bn0 + wni * 32 + ni * 8 + 2 * q;
            float v0 = acc[mi][ni][0] + bias[cg];
            float v1 = acc[mi][ni][1] + bias[cg + 1];
            float v2 = acc[mi][ni][2] + bias[cg];
            float v3 = acc[mi][ni][3] + bias[cg + 1];
            if (ACT == 1) { v0 = lrelu(v0); v1 = lrelu(v1); v2 = lrelu(v2); v3 = lrelu(v3); }
            if (STATS) {
                cs[ni][0] += v0 + v2; cs[ni][1] += v1 + v3;
                cq[ni][0] += v0 * v0 + v2 * v2;
                cq[ni][1] += v1 * v1 + v3 * v3;
            }
            if (OUTS == 1) {
                __half h0, l0, h1, l1;
                int wi = (coloff + cg) >> 1;
                split_h(v0, h0, l0); split_h(v1, h1, l1);
                size_t w = aidx(r0, wi, KPc);
                ((uint32_t*)Chi)[w] = pack2(h0, h1);
                ((uint32_t*)Clo)[w] = pack2(l0, l1);
                split_h(v2, h0, l0); split_h(v3, h1, l1);
                w = aidx(r0 + 8, wi, KPc);
                ((uint32_t*)Chi)[w] = pack2(h0, h1);
                ((uint32_t*)Clo)[w] = pack2(l0, l1);
            } else {
                float2 a; a.x = v0; a.y = v1;
                float2 b; b.x = v2; b.y = v3;
                *(float2*)(Cf + (size_t)r0 * ldc + cg) = a;
                *(float2*)(Cf + (size_t)(r0 + 8) * ldc + cg) = b;
            }
        }
    }
    if (STATS) {
        #pragma unroll
        for (int ni = 0; ni < 4; ni++) {
            #pragma unroll
            for (int j = 0; j < 2; j++) {
                #pragma unroll
                for (int off = 16; off >= 4; off >>= 1) {
                    cs[ni][j] += __shfl_down_sync(0xffffffffu, cs[ni][j], off);
                    cq[ni][j] += __shfl_down_sync(0xffffffffu, cq[ni][j], off);
                }
            }
        }
        if (lane < 4) {
            #pragma unroll
            for (int ni = 0; ni < 4; ni++) {
                int cg = bn0 + wni * 32 + ni * 8 + 2 * q;
                atomicAdd(&stp[cg], cs[ni][0]);
                atomicAdd(&stp[cg + 1], cs[ni][1]);
                atomicAdd(&stp[ldc + cg], cq[ni][0]);
                atomicAdd(&stp[ldc + cg + 1], cq[ni][1]);
            }
        }
    }
}

// ---------------- launch ----------------
extern "C" void kernel_launch(void* const* d_in, const int* in_sizes, int n_in,
                              void* d_out, int out_size) {
    (void)in_sizes; (void)n_in; (void)out_size;
    const int*   d_index  = (const int*)d_in[0];
    const int*   p_index  = (const int*)d_in[1];
    const float* d_vecs   = (const float*)d_in[2];
    const float* p_emb    = (const float*)d_in[3];
    const float* d_ecfps  = (const float*)d_in[4];
    const int*   d_ei     = (const int*)d_in[5];
    const float* d_ew     = (const float*)d_in[6];
    const float* p_gos    = (const float*)d_in[7];
    const int*   p_ei     = (const int*)d_in[8];
    const float* p_ew     = (const float*)d_in[9];
    const float* W_dg     = (const float*)d_in[10];
    const float* b_dg     = (const float*)d_in[11];
    const float* W_pg     = (const float*)d_in[12];
    const float* b_pg     = (const float*)d_in[13];
    const float* W_e1     = (const float*)d_in[14];
    const float* b_e1     = (const float*)d_in[15];
    const float* g_e1     = (const float*)d_in[16];
    const float* be_e1    = (const float*)d_in[17];
    const float* W_e2     = (const float*)d_in[18];
    const float* b_e2     = (const float*)d_in[19];
    const float* g_e2     = (const float*)d_in[20];
    const float* be_e2    = (const float*)d_in[21];
    const float* W_o1     = (const float*)d_in[22];
    const float* b_o1     = (const float*)d_in[23];
    const float* g_o      = (const float*)d_in[24];
    const float* be_o     = (const float*)d_in[25];
    const float* W_o2     = (const float*)d_in[26];
    const float* b_o2     = (const float*)d_in[27];

    float* out = (float*)d_out;
    float* y_out = out;
    float* feat_out = out + BB;

    float *degd, *degp, *z1, *z2, *z3, *stats;
    int *cntd, *cntp, *ebufd, *ebufp;
    __half *Gdh, *Gdl, *Gph, *Gpl, *F0h, *F0l, *Z1h, *Z1l, *Fh, *Fl;
    __half *Wdgh, *Wpgh, *We1h, *We2h, *Wo1h;
    cudaGetSymbolAddress((void**)&degd, g_degd);
    cudaGetSymbolAddress((void**)&degp, g_degp);
    cudaGetSymbolAddress((void**)&cntd, g_cntd);
    cudaGetSymbolAddress((void**)&cntp, g_cntp);
    cudaGetSymbolAddress((void**)&ebufd, g_ebufd);
    cudaGetSymbolAddress((void**)&ebufp, g_ebufp);
    cudaGetSymbolAddress((void**)&z1, g_z1);
    cudaGetSymbolAddress((void**)&z2, g_z2);
    cudaGetSymbolAddress((void**)&z3, g_z3);
    cudaGetSymbolAddress((void**)&stats, g_stats);
    cudaGetSymbolAddress((void**)&Gdh, g_Gdh); cudaGetSymbolAddress((void**)&Gdl, g_Gdl);
    cudaGetSymbolAddress((void**)&Gph, g_Gph); cudaGetSymbolAddress((void**)&Gpl, g_Gpl);
    cudaGetSymbolAddress((void**)&F0h, g_F0h); cudaGetSymbolAddress((void**)&F0l, g_F0l);
    cudaGetSymbolAddress((void**)&Z1h, g_Z1h); cudaGetSymbolAddress((void**)&Z1l, g_Z1l);
    cudaGetSymbolAddress((void**)&Fh, g_Fh);   cudaGetSymbolAddress((void**)&Fl, g_Fl);
    cudaGetSymbolAddress((void**)&Wdgh, g_Wdgh);
    cudaGetSymbolAddress((void**)&Wpgh, g_Wpgh);
    cudaGetSymbolAddress((void**)&We1h, g_We1h);
    cudaGetSymbolAddress((void**)&We2h, g_We2h);
    cudaGetSymbolAddress((void**)&Wo1h, g_Wo1h);

    float* stats1 = stats;          // e1: 2048 cols
    float* stats2 = stats + 4096;   // e2: 1024 cols
    float* stats3 = stats + 6144;   // o:  256 cols

    static cudaStream_t s1 = nullptr;
    static cudaEvent_t evA = nullptr, evW = nullptr, evDeg = nullptr, evP = nullptr,
                       evGd = nullptr, evC = nullptr, evZ = nullptr;
    static bool attr_done = false;
    if (!attr_done) {
        cudaFuncSetAttribute(fgemm_k<1, 1, 0>, cudaFuncAttributeMaxDynamicSharedMemorySize, FG_SMEM);
        cudaFuncSetAttribute(fgemm_k<0, 0, 1>, cudaFuncAttributeMaxDynamicSharedMemorySize, FG_SMEM);
        cudaFuncSetAttribute(fgemm_k<1, 0, 1>, cudaFuncAttributeMaxDynamicSharedMemorySize, FG_SMEM);
        cudaStreamCreateWithFlags(&s1, cudaStreamNonBlocking);
        cudaEventCreateWithFlags(&evA, cudaEventDisableTiming);
        cudaEventCreateWithFlags(&evW, cudaEventDisableTiming);
        cudaEventCreateWithFlags(&evDeg, cudaEventDisableTiming);
        cudaEventCreateWithFlags(&evP, cudaEventDisableTiming);
        cudaEventCreateWithFlags(&evGd, cudaEventDisableTiming);
        cudaEventCreateWithFlags(&evC, cudaEventDisableTiming);
        cudaEventCreateWithFlags(&evZ, cudaEventDisableTiming);
        attr_done = true;
    }

    // ---- fork: side stream s1 does GCN weight conversions first ----
    cudaEventRecord(evA, 0);
    cudaStreamWaitEvent(s1, evA, 0);
    wsplit_bt_k<<<((long)1024 * (KP_GD / 2) + 255) / 256, 256, 0, s1>>>(W_dg, Wdgh, 1024, 1024, KP_GD);
    wsplit_bt_k<<<((long)1024 * (KP_GP / 2) + 255) / 256, 256, 0, s1>>>(W_pg, Wpgh, 2812, 1024, KP_GP);
    cudaEventRecord(evW, s1);

    // ---- main stream: fused stats-zero + edge buckets (deg/cnt pre-zeroed) ----
    degbucket_k<<<(ED + 255) / 256, 256>>>(d_ei, d_ew, p_ei, p_ew, degd, degp,
                                           cntd, cntp, ebufd, ebufp, stats);
    cudaEventRecord(evDeg, 0);

    // ---- s1: gather_p (concurrent with main's gather_d/gcn_d), then remaining prep ----
    cudaStreamWaitEvent(s1, evDeg, 0);
    gcn_gather_split_k<<<BB, 256, 0, s1>>>(p_gos, degp, cntp, ebufp, p_ei, p_ew, p_index,
                                           Gph, Gpl, 2812, KP_GP, CAP_P);
    cudaEventRecord(evP, s1);
    copy_base_split_k<<<((long)BB * 672 + 255) / 256, 256, 0, s1>>>(d_vecs, p_emb, F0h, F0l);
    wsplit_bt_k<<<((long)2048 * (KP_F0 / 2) + 255) / 256, 256, 0, s1>>>(W_e1, We1h, 3372, 2048, KP_F0);
    wsplit_bt_k<<<((long)1024 * (KP_Z1 / 2) + 255) / 256, 256, 0, s1>>>(W_e2, We2h, 2048, 1024, KP_Z1);
    wsplit_bt_k<<<((long)256 * (KP_F / 2) + 255) / 256, 256, 0, s1>>>(W_o1, Wo1h, 1024, 256, KP_F);
    cudaEventRecord(evC, s1);

    // ---- main: gather_d, then d-branch GEMM ----
    gcn_gather_split_k<<<BB, 256>>>(d_ecfps, degd, cntd, ebufd, d_ei, d_ew, d_index,
                                    Gdh, Gdl, 1024, KP_GD, CAP_D);
    cudaEventRecord(evGd, 0);
    cudaStreamWaitEvent(0, evW, 0);
    fgemm_k<1, 1, 0><<<dim3(8, 16), 512, FG_SMEM>>>((const uint32_t*)Gdh, (const uint32_t*)Gdl,
        (const uint32_t*)Wdgh, b_dg, nullptr, F0h, F0l, nullptr, KP_GD, 0, KP_F0, 1324);
    cudaStreamWaitEvent(0, evP, 0);
    fgemm_k<1, 1, 0><<<dim3(8, 16), 512, FG_SMEM>>>((const uint32_t*)Gph, (const uint32_t*)Gpl,
        (const uint32_t*)Wpgh, b_pg, nullptr, F0h, F0l, nullptr, KP_GP, 0, KP_F0, 2348);

    // ---- s1 tail: restore deg/cnt to zero (after both gathers are done), then join ----
    cudaStreamWaitEvent(s1, evGd, 0);   // gather_d done (gather_p already in s1 order)
    zero_dc_k<<<(ND + 255) / 256, 256, 0, s1>>>(degd, degp, cntd, cntp);
    cudaEventRecord(evZ, s1);

    // ---- e1 (needs copy_base + We1 from s1) ----
    cudaStreamWaitEvent(0, evC, 0);
    fgemm_k<0, 0, 1><<<dim3(16, 16), 512, FG_SMEM>>>((const uint32_t*)F0h, (const uint32_t*)F0l,
        (const uint32_t*)We1h, b_e1, z1, nullptr, nullptr, stats1, KP_F0, 2048, 0, 0);
    bn_apply_split_k<0><<<((long)BB * 1024 + 255) / 256, 256>>>(z1, stats1, g_e1, be_e1,
        Z1h, Z1l, nullptr, 2048);

    // e2 -> feature (d_out)
    fgemm_k<0, 0, 1><<<dim3(8, 16), 512, FG_SMEM>>>((const uint32_t*)Z1h, (const uint32_t*)Z1l,
        (const uint32_t*)We2h, b_e2, z2, nullptr, nullptr, stats2, KP_Z1, 1024, 0, 0);
    bn_apply_split_k<1><<<((long)BB * 512 + 255) / 256, 256>>>(z2, stats2, g_e2, be_e2,
        Fh, Fl, feat_out, 1024);

    // output head: GEMM (leaky+stats fused) then fused BN+dot
    fgemm_k<1, 0, 1><<<dim3(2, 16), 512, FG_SMEM>>>((const uint32_t*)Fh, (const uint32_t*)Fl,
        (const uint32_t*)Wo1h, b_o1, z3, nullptr, nullptr, stats3, KP_F, 256, 0, 0);
    // join s1's zero_dc tail before the final kernel (all side-stream work joined)
    cudaStreamWaitEvent(0, evZ, 0);
    bn_out_k<<<(BB * 32 + 255) / 256, 256>>>(z3, stats3, g_o, be_o, W_o2, b_o2, y_out);
}